// round 2
// baseline (speedup 1.0000x reference)
#include <cuda_runtime.h>
#include <math.h>

#define GX 200
#define GY 200
#define GZ 20
#define NVOX (GX*GY*GZ)               // 800000
#define NCH 8
#define TOTAL_OUT (NVOX * (1 + NCH))  // 7,200,000 floats
#define MAXG 32768

// Per-Gaussian compact record, 5 x float4 = 80B:
// rec[0] = {mx, my, mz, op}
// rec[1] = {i00, i01, i02, i11}
// rec[2] = {i12, i22, bits(base: ixmin|iymin<<8|izmin<<16), bits(cnt: cx|cy<<8|cz<<16)}
// rec[3] = feats[0..3], rec[4] = feats[4..7]
__device__ float4 g_rec[MAXG * 5];

__device__ __forceinline__ void red_add_v4(float* addr, float a, float b, float c, float d) {
    asm volatile("red.global.add.v4.f32 [%0], {%1,%2,%3,%4};"
                 :: "l"(addr), "f"(a), "f"(b), "f"(c), "f"(d) : "memory");
}
__device__ __forceinline__ void red_add_v2(float* addr, float a, float b) {
    asm volatile("red.global.add.v2.f32 [%0], {%1,%2};"
                 :: "l"(addr), "f"(a), "f"(b) : "memory");
}

__global__ void prep_kernel(const float* __restrict__ means, const float* __restrict__ opac,
                            const float* __restrict__ scales, const float* __restrict__ rots,
                            const float* __restrict__ feats, int N)
{
    int g = blockIdx.x * blockDim.x + threadIdx.x;
    if (g >= N) return;
    float4* rec = g_rec + g * 5;

    float mx = means[3*g+0], my = means[3*g+1], mz = means[3*g+2];
    float op = opac[g];
    float sx = scales[3*g+0], sy = scales[3*g+1], sz = scales[3*g+2];
    float qr = rots[4*g+0], qx = rots[4*g+1], qy = rots[4*g+2], qz = rots[4*g+3];

    float qn = rsqrtf(qr*qr + qx*qx + qy*qy + qz*qz + 1e-8f);
    qr *= qn; qx *= qn; qy *= qn; qz *= qn;

    float r00 = 1.f - 2.f*(qy*qy + qz*qz), r01 = 2.f*(qx*qy - qr*qz), r02 = 2.f*(qx*qz + qr*qy);
    float r10 = 2.f*(qx*qy + qr*qz), r11 = 1.f - 2.f*(qx*qx + qz*qz), r12 = 2.f*(qy*qz - qr*qx);
    float r20 = 2.f*(qx*qz - qr*qy), r21 = 2.f*(qy*qz + qr*qx), r22 = 1.f - 2.f*(qx*qx + qy*qy);

    float sx2 = sx*sx, sy2 = sy*sy, sz2 = sz*sz;
    float c00 = r00*r00*sx2 + r01*r01*sy2 + r02*r02*sz2;
    float c01 = r00*r10*sx2 + r01*r11*sy2 + r02*r12*sz2;
    float c02 = r00*r20*sx2 + r01*r21*sy2 + r02*r22*sz2;
    float c11 = r10*r10*sx2 + r11*r11*sy2 + r12*r12*sz2;
    float c12 = r10*r20*sx2 + r11*r21*sy2 + r12*r22*sz2;
    float c22 = r20*r20*sx2 + r21*r21*sy2 + r22*r22*sz2;

    float sdx = sqrtf(c00), sdy = sqrtf(c11), sdz = sqrtf(c22);
    float bminx = mx - 3.f*sdx, bminy = my - 3.f*sdy, bminz = mz - 3.f*sdz;
    float bmaxx = mx + 3.f*sdx, bmaxy = my + 3.f*sdy, bmaxz = mz + 3.f*sdz;

    bool keep = (bmaxx > -40.f) && (bmaxy > -40.f) && (bmaxz > -4.f)
             && (bminx <  40.f) && (bminy <  40.f) && (bminz <  4.f)
             && (op > 1e-4f);
    if (!keep) { rec[2] = make_float4(0.f, 0.f, 0.f, __int_as_float(0)); return; }

    float m00 = c11*c22 - c12*c12;
    float m01 = c02*c12 - c01*c22;
    float m02 = c01*c12 - c02*c11;
    float det = c00*m00 + c01*m01 + c02*m02;
    float idet = 1.0f / det;
    float i00 = m00 * idet;
    float i01 = m01 * idet;
    float i02 = m02 * idet;
    float i11 = (c00*c22 - c02*c02) * idet;
    float i12 = (c01*c02 - c00*c12) * idet;
    float i22 = (c00*c11 - c01*c01) * idet;

    // IEEE division + trunc-toward-zero matches jnp int32 cast
    int ixmin = max((int)__fdiv_rn(bminx + 40.f, 0.4f), 0);
    int iymin = max((int)__fdiv_rn(bminy + 40.f, 0.4f), 0);
    int izmin = max((int)__fdiv_rn(bminz +  4.f, 0.4f), 0);
    int ixmax = min((int)__fdiv_rn(bmaxx + 40.f, 0.4f), GX - 1);
    int iymax = min((int)__fdiv_rn(bmaxy + 40.f, 0.4f), GY - 1);
    int izmax = min((int)__fdiv_rn(bmaxz +  4.f, 0.4f), GZ - 1);

    int cx = min(ixmax - ixmin + 1, 8);
    int cy = min(iymax - iymin + 1, 8);
    int cz = min(izmax - izmin + 1, 8);

    int base = ixmin | (iymin << 8) | (izmin << 16);
    int cnt  = cx | (cy << 8) | (cz << 16);

    const float4* fptr = (const float4*)(feats + 8*g);
    rec[0] = make_float4(mx, my, mz, op);
    rec[1] = make_float4(i00, i01, i02, i11);
    rec[2] = make_float4(i12, i22, __int_as_float(base), __int_as_float(cnt));
    rec[3] = fptr[0];
    rec[4] = fptr[1];
}

__global__ __launch_bounds__(256) void vox_kernel(float* __restrict__ density,
                                                  float* __restrict__ gfeat, int N)
{
    int g    = (blockIdx.x * blockDim.x + threadIdx.x) >> 5;
    int lane = threadIdx.x & 31;
    if (g >= N) return;

    const float4* rec = g_rec + g * 5;
    float4 A  = rec[0];   // mx,my,mz,op
    float4 Bv = rec[1];   // i00,i01,i02,i11
    float4 Cv = rec[2];   // i12,i22, base, cnt
    int cnt = __float_as_int(Cv.w);
    if (cnt == 0) return;
    float4 F0 = rec[3];
    float4 F1 = rec[4];

    float mx = A.x, my = A.y, mz = A.z, op = A.w;
    float i00 = Bv.x, i01 = Bv.y, i02 = Bv.z, i11 = Bv.w;
    float i12 = Cv.x, i22 = Cv.y;
    int base  = __float_as_int(Cv.z);
    int ixmin = base & 255, iymin = (base >> 8) & 255, izmin = (base >> 16) & 255;
    int cx = cnt & 255, cy = (cnt >> 8) & 255, cz = (cnt >> 16) & 255;

    // z pairing on even boundaries so red.v2 stays 8B-aligned (GZ even => flat parity == z parity)
    int zend   = izmin + cz;
    int zbase  = izmin & ~1;
    int npairs = (zend + 1 - zbase) >> 1;
    int P = cx * cy * npairs;

    for (int p = lane; p < P; p += 32) {
        int pz = p % npairs;
        int t  = p / npairs;
        int oy = t % cy;
        int ox = t / cy;
        int ix = ixmin + ox, iy = iymin + oy;
        int z0 = zbase + 2*pz, z1 = z0 + 1;
        bool v0 = (z0 >= izmin);
        bool v1 = (z1 < zend);

        float cxp = (float)ix * 0.4f - 39.8f;
        float cyp = (float)iy * 0.4f - 39.8f;
        float dx = cxp - mx, dy = cyp - my;

        // per-column quadratic in dz: maha = qc + lin*dz + i22*dz*dz
        float qc  = i00*dx*dx + 2.f*i01*dx*dy + i11*dy*dy;
        float lin = 2.f*(i02*dx + i12*dy);

        float dz0 = ((float)z0 * 0.4f - 3.8f) - mz;
        float dz1 = dz0 + 0.4f;
        float w0 = v0 ? op * expf(-0.5f * (qc + dz0*(lin + i22*dz0))) : 0.f;
        float w1 = v1 ? op * expf(-0.5f * (qc + dz1*(lin + i22*dz1))) : 0.f;

        int flat0 = (ix * GY + iy) * GZ + z0;
        if (v0 && v1) {
            red_add_v2(density + flat0, w0, w1);
        } else if (v0) {
            atomicAdd(density + flat0, w0);
        } else {
            atomicAdd(density + flat0 + 1, w1);
        }
        if (v0) {
            float* fp = gfeat + (size_t)flat0 * NCH;
            red_add_v4(fp,     w0*F0.x, w0*F0.y, w0*F0.z, w0*F0.w);
            red_add_v4(fp + 4, w0*F1.x, w0*F1.y, w0*F1.z, w0*F1.w);
        }
        if (v1) {
            float* fp = gfeat + (size_t)(flat0 + 1) * NCH;
            red_add_v4(fp,     w1*F0.x, w1*F0.y, w1*F0.z, w1*F0.w);
            red_add_v4(fp + 4, w1*F1.x, w1*F1.y, w1*F1.z, w1*F1.w);
        }
    }
}

__global__ void finalize_kernel(const float4* __restrict__ density4, float* __restrict__ gfeat) {
    int q = blockIdx.x * blockDim.x + threadIdx.x;   // 4 voxels per thread
    if (q >= NVOX / 4) return;
    float4 d = density4[q];
    float inv0 = 1.0f / fmaxf(d.x, 1e-6f);
    float inv1 = 1.0f / fmaxf(d.y, 1e-6f);
    float inv2 = 1.0f / fmaxf(d.z, 1e-6f);
    float inv3 = 1.0f / fmaxf(d.w, 1e-6f);
    float4* fp = (float4*)(gfeat + (size_t)q * 4 * NCH);
    #pragma unroll
    for (int j = 0; j < 4; j++) {
        float inv = (j == 0) ? inv0 : (j == 1) ? inv1 : (j == 2) ? inv2 : inv3;
        float4 a = fp[2*j], b = fp[2*j+1];
        a.x *= inv; a.y *= inv; a.z *= inv; a.w *= inv;
        b.x *= inv; b.y *= inv; b.z *= inv; b.w *= inv;
        fp[2*j]   = a;
        fp[2*j+1] = b;
    }
}

extern "C" void kernel_launch(void* const* d_in, const int* in_sizes, int n_in,
                              void* d_out, int out_size) {
    const float* means  = (const float*)d_in[0];
    const float* opac   = (const float*)d_in[1];
    const float* scales = (const float*)d_in[2];
    const float* rots   = (const float*)d_in[3];
    const float* feats  = (const float*)d_in[4];

    float* density = (float*)d_out;
    float* gfeat   = density + NVOX;

    int N = in_sizes[1];
    if (N > MAXG) N = MAXG;

    cudaMemsetAsync(d_out, 0, (size_t)TOTAL_OUT * sizeof(float), 0);

    prep_kernel<<<(N + 255) / 256, 256>>>(means, opac, scales, rots, feats, N);

    int threads = N * 32;
    vox_kernel<<<(threads + 255) / 256, 256>>>(density, gfeat, N);

    finalize_kernel<<<(NVOX/4 + 255) / 256, 256>>>((const float4*)d_out, gfeat);
}

// round 3
// speedup vs baseline: 1.4293x; 1.4293x over previous
#include <cuda_runtime.h>
#include <math.h>

#define GX 200
#define GY 200
#define GZ 20
#define NVOX (GX*GY*GZ)               // 800000
#define NCH 8
#define TOTAL_OUT (NVOX * (1 + NCH))  // 7,200,000 floats

// Vector float4 reduction to global memory (sm_90+ PTX).
__device__ __forceinline__ void red_add_v4(float* addr, float a, float b, float c, float d) {
    asm volatile("red.global.add.v4.f32 [%0], {%1,%2,%3,%4};"
                 :: "l"(addr), "f"(a), "f"(b), "f"(c), "f"(d) : "memory");
}

__global__ __launch_bounds__(256) void vox_kernel(
    const float* __restrict__ means, const float* __restrict__ opac,
    const float* __restrict__ scales, const float* __restrict__ rots,
    const float* __restrict__ feats,
    float* __restrict__ density, float* __restrict__ gfeat, int N)
{
    int g    = (blockIdx.x * blockDim.x + threadIdx.x) >> 5;
    int lane = threadIdx.x & 31;
    if (g >= N) return;

    // ---- per-Gaussian setup (redundant across lanes; broadcast loads) ----
    float mx = means[3*g+0], my = means[3*g+1], mz = means[3*g+2];
    float op = opac[g];
    float sx = scales[3*g+0], sy = scales[3*g+1], sz = scales[3*g+2];
    float qr = rots[4*g+0], qx = rots[4*g+1], qy = rots[4*g+2], qz = rots[4*g+3];

    float qn = rsqrtf(qr*qr + qx*qx + qy*qy + qz*qz + 1e-8f);
    qr *= qn; qx *= qn; qy *= qn; qz *= qn;

    float r00 = 1.f - 2.f*(qy*qy + qz*qz), r01 = 2.f*(qx*qy - qr*qz), r02 = 2.f*(qx*qz + qr*qy);
    float r10 = 2.f*(qx*qy + qr*qz), r11 = 1.f - 2.f*(qx*qx + qz*qz), r12 = 2.f*(qy*qz - qr*qx);
    float r20 = 2.f*(qx*qz - qr*qy), r21 = 2.f*(qy*qz + qr*qx), r22 = 1.f - 2.f*(qx*qx + qy*qy);

    float sx2 = sx*sx, sy2 = sy*sy, sz2 = sz*sz;
    // cov = R diag(s^2) R^T (symmetric)
    float c00 = r00*r00*sx2 + r01*r01*sy2 + r02*r02*sz2;
    float c01 = r00*r10*sx2 + r01*r11*sy2 + r02*r12*sz2;
    float c02 = r00*r20*sx2 + r01*r21*sy2 + r02*r22*sz2;
    float c11 = r10*r10*sx2 + r11*r11*sy2 + r12*r12*sz2;
    float c12 = r10*r20*sx2 + r11*r21*sy2 + r12*r22*sz2;
    float c22 = r20*r20*sx2 + r21*r21*sy2 + r22*r22*sz2;

    float sdx = sqrtf(c00), sdy = sqrtf(c11), sdz = sqrtf(c22);
    float bminx = mx - 3.f*sdx, bminy = my - 3.f*sdy, bminz = mz - 3.f*sdz;
    float bmaxx = mx + 3.f*sdx, bmaxy = my + 3.f*sdy, bmaxz = mz + 3.f*sdz;

    // keep mask (filter_gaussians): bbox overlaps volume, opacity above threshold
    bool keep = (bmaxx > -40.f) && (bmaxy > -40.f) && (bmaxz > -4.f)
             && (bminx <  40.f) && (bminy <  40.f) && (bminz <  4.f)
             && (op > 1e-4f);
    if (!keep) return;

    // 3x3 symmetric inverse via adjugate
    float m00 = c11*c22 - c12*c12;
    float m01 = c02*c12 - c01*c22;
    float m02 = c01*c12 - c02*c11;
    float det = c00*m00 + c01*m01 + c02*m02;
    float idet = 1.0f / det;
    float i00 = m00 * idet;
    float i01 = m01 * idet;
    float i02 = m02 * idet;
    float i11 = (c00*c22 - c02*c02) * idet;
    float i12 = (c01*c02 - c00*c12) * idet;
    float i22 = (c00*c11 - c01*c01) * idet;

    // voxel index bounds; IEEE division + trunc-toward-zero matches jnp .astype(int32)
    int ixmin = max((int)__fdiv_rn(bminx + 40.f, 0.4f), 0);
    int iymin = max((int)__fdiv_rn(bminy + 40.f, 0.4f), 0);
    int izmin = max((int)__fdiv_rn(bminz +  4.f, 0.4f), 0);
    int ixmax = min((int)__fdiv_rn(bmaxx + 40.f, 0.4f), GX - 1);
    int iymax = min((int)__fdiv_rn(bmaxy + 40.f, 0.4f), GY - 1);
    int izmax = min((int)__fdiv_rn(bmaxz +  4.f, 0.4f), GZ - 1);

    int cx = min(ixmax - ixmin + 1, 8);
    int cy = min(iymax - iymin + 1, 8);
    int cz = min(izmax - izmin + 1, 8);
    int P = cx * cy * cz;

    // Magic-number reciprocals for division by cz / cy.
    // m = ceil(2^16 / d): exact n/d = (n*m)>>16 for d in [1,8], n <= 512.
    unsigned mcz = (65535u / (unsigned)cz) + 1u;
    unsigned mcy = (65535u / (unsigned)cy) + 1u;

    const float4* fptr = (const float4*)(feats + 8*g);
    float4 f0 = fptr[0];
    float4 f1 = fptr[1];

    for (int p = lane; p < P; p += 32) {
        unsigned t  = ((unsigned)p * mcz) >> 16;   // p / cz
        int oz = p - (int)t * cz;                  // p % cz
        unsigned ox = (t * mcy) >> 16;             // t / cy
        int oy = (int)t - (int)ox * cy;            // t % cy
        int ix = ixmin + (int)ox, iy = iymin + oy, iz = izmin + oz;

        float cxp = ((float)ix * 0.4f + (-40.f)) + 0.2f;
        float cyp = ((float)iy * 0.4f + (-40.f)) + 0.2f;
        float czp = ((float)iz * 0.4f + ( -4.f)) + 0.2f;

        float dx = cxp - mx, dy = cyp - my, dz = czp - mz;
        float maha = i00*dx*dx + i11*dy*dy + i22*dz*dz
                   + 2.f*(i01*dx*dy + i02*dx*dz + i12*dy*dz);
        float w = op * __expf(-0.5f * maha);

        int flat = (ix * GY + iy) * GZ + iz;
        atomicAdd(density + flat, w);
        float* fp = gfeat + (size_t)flat * NCH;
        red_add_v4(fp,     w*f0.x, w*f0.y, w*f0.z, w*f0.w);
        red_add_v4(fp + 4, w*f1.x, w*f1.y, w*f1.z, w*f1.w);
    }
}

__global__ void finalize_kernel(const float* __restrict__ density, float* __restrict__ gfeat) {
    int v = blockIdx.x * blockDim.x + threadIdx.x;
    if (v >= NVOX) return;
    float d   = fmaxf(density[v], 1e-6f);
    float inv = 1.0f / d;
    float4* fp = (float4*)(gfeat + (size_t)v * NCH);
    float4 a = fp[0], b = fp[1];
    a.x *= inv; a.y *= inv; a.z *= inv; a.w *= inv;
    b.x *= inv; b.y *= inv; b.z *= inv; b.w *= inv;
    fp[0] = a;
    fp[1] = b;
}

extern "C" void kernel_launch(void* const* d_in, const int* in_sizes, int n_in,
                              void* d_out, int out_size) {
    const float* means  = (const float*)d_in[0];
    const float* opac   = (const float*)d_in[1];
    const float* scales = (const float*)d_in[2];
    const float* rots   = (const float*)d_in[3];
    const float* feats  = (const float*)d_in[4];

    float* density = (float*)d_out;
    float* gfeat   = density + NVOX;

    int N = in_sizes[1];  // opacities: B*N*1 elements

    cudaMemsetAsync(d_out, 0, (size_t)TOTAL_OUT * sizeof(float), 0);

    int threads = N * 32;  // one warp per Gaussian
    vox_kernel<<<(threads + 255) / 256, 256>>>(means, opac, scales, rots, feats,
                                               density, gfeat, N);

    finalize_kernel<<<(NVOX + 255) / 256, 256>>>(density, gfeat);
}